// round 16
// baseline (speedup 1.0000x reference)
#include <cuda_runtime.h>
#include <math.h>

#define Nn 4
#define Ll 2048
#define Hh 8
#define Dd 128
#define PAIRS 32           // Nn*Hh
#define DE 384             // effective feature dim (3 branches x 128)
#define CH 64              // chunk length
#define NCH 32             // Ll / CH
#define EPSF 1e-6f

// ---- scratch (static device allocations; no cudaMalloc allowed) ----
__device__ float g_Qf[(size_t)PAIRS * Ll * DE];          // ~100.7 MB
__device__ float g_Kf[(size_t)PAIRS * Ll * DE];          // ~100.7 MB
__device__ float g_S [(size_t)PAIRS * NCH * DE * Dd];    // ~201 MB  chunk KV states
__device__ float g_Ks[(size_t)PAIRS * NCH * DE];         // chunk K column sums
__device__ float g_osum[Hh * Dd];

__device__ __forceinline__ float elu1(float x) { return x > 0.0f ? x + 1.0f : expf(x); }

// ---------------------------------------------------------------------------
// Kernel 0: omsum[h][j] = sum_i omega[h][i][j]
// ---------------------------------------------------------------------------
__global__ void k_omsum(const float* __restrict__ OMEGA)
{
    int h = blockIdx.x, j = threadIdx.x;
    const float* base = OMEGA + (size_t)h * Dd * Dd + j;
    float s = 0.0f;
    for (int i = 0; i < Dd; i++) s += base[(size_t)i * Dd];
    g_osum[h * Dd + j] = s;
}

// ---------------------------------------------------------------------------
// Kernel 1: features. q2_proj GEMM (tiled) + trig epilogue -> g_Qf, g_Kf
// grid: (Ll/32, PAIRS), 256 threads. Thread (ty,tx) owns 4 l x 4 j.
// ---------------------------------------------------------------------------
__global__ void __launch_bounds__(256) k_feat(
    const float* __restrict__ Q, const float* __restrict__ Q2,
    const float* __restrict__ K, const float* __restrict__ KLEN,
    const float* __restrict__ OMEGA)
{
    __shared__ float Wt[32][132];   // omega tile [i][j]
    __shared__ float Q2t[32][36];   // q2 tile [l][i]
    __shared__ float osm[128];

    const int p = blockIdx.y;
    const int n = p >> 3, h = p & 7;
    const int l0g = blockIdx.x * 32;
    const int tid = threadIdx.x;
    const int tx = tid & 31, ty = tid >> 5;   // tx 0..31 (j-groups), ty 0..7 (l-groups)

    if (tid < 128) osm[tid] = g_osum[h * Dd + tid];

    const float* omh = OMEGA + (size_t)h * Dd * Dd;
    float acc[4][4] = {};

    for (int i0 = 0; i0 < Dd; i0 += 32) {
        __syncthreads();
        {
            int c4 = tid & 31;
            int r0 = tid >> 5;
            #pragma unroll
            for (int rep = 0; rep < 4; rep++) {
                int row = r0 + rep * 8;
                float4 w = *(const float4*)(omh + (size_t)(i0 + row) * Dd + c4 * 4);
                *(float4*)&Wt[row][c4 * 4] = w;
            }
            int row = tid >> 3;
            int c4b = tid & 7;
            float4 qv = *(const float4*)(Q2 + (((size_t)(n * Ll + l0g + row) * Hh) + h) * Dd + i0 + c4b * 4);
            *(float4*)&Q2t[row][c4b * 4] = qv;
        }
        __syncthreads();
        #pragma unroll
        for (int i = 0; i < 32; i++) {
            float w[4];
            *(float4*)w = *(float4*)&Wt[i][tx * 4];
            #pragma unroll
            for (int li = 0; li < 4; li++) {
                float qv = Q2t[ty * 4 + li][i];
                #pragma unroll
                for (int jj = 0; jj < 4; jj++)
                    acc[li][jj] = fmaf(qv, w[jj], acc[li][jj]);
            }
        }
    }

    const int j0 = tx * 4;
    #pragma unroll
    for (int li = 0; li < 4; li++) {
        int lg = l0g + ty * 4 + li;
        size_t ib = (((size_t)(n * Ll + lg) * Hh) + h) * Dd + j0;
        float4 qv = *(const float4*)(Q + ib);
        float4 kv = *(const float4*)(K + ib);
        float kl = KLEN[n * Ll + lg];
        float dl = (float)lg * (1.0f / (float)Ll);
        float qa[4] = {qv.x, qv.y, qv.z, qv.w};
        float ka[4] = {kv.x, kv.y, kv.z, kv.w};
        float qf0[4], qf1[4], qf2[4], kf0[4], kf1[4], kf2[4];
        #pragma unroll
        for (int jj = 0; jj < 4; jj++) {
            float t = dl * osm[j0 + jj];
            float s, c;
            sincosf(t, &s, &c);
            float sq = sinf(acc[li][jj]);           // sin(q2_proj)
            float A = sq * sq * elu1(qa[jj]);       // Q_term
            float B = elu1(ka[jj]) * kl;            // K feature
            float s2 = s * s, c2 = c * c, sc = s * c;
            qf0[jj] = A * s2;  qf1[jj] = A * c2;  qf2[jj] = -2.0f * A * sc;
            kf0[jj] = B * c2;  kf1[jj] = B * s2;  kf2[jj] = B * sc;
        }
        size_t ob = ((size_t)p * Ll + lg) * DE + j0;
        *(float4*)(g_Qf + ob)       = *(float4*)qf0;
        *(float4*)(g_Qf + ob + 128) = *(float4*)qf1;
        *(float4*)(g_Qf + ob + 256) = *(float4*)qf2;
        *(float4*)(g_Kf + ob)       = *(float4*)kf0;
        *(float4*)(g_Kf + ob + 128) = *(float4*)kf1;
        *(float4*)(g_Kf + ob + 256) = *(float4*)kf2;
    }
}

// ---------------------------------------------------------------------------
// Kernel A: per (chunk, pair, branch) compute S_c = K_c^T V_c  (128x128) and
// K column sums. grid: (NCH, PAIRS, 3), 256 threads, 8x8 micro-tile.
// ---------------------------------------------------------------------------
__global__ void __launch_bounds__(256) k_chunkKV(const float* __restrict__ V)
{
    __shared__ float Kt[16][132];
    __shared__ float Vt[16][132];
    const int c = blockIdx.x, p = blockIdx.y, z = blockIdx.z;
    const int n = p >> 3, h = p & 7;
    const int tid = threadIdx.x;
    const int tx = tid & 15, ty = tid >> 4;
    const int i0 = ty * 8, j0 = tx * 8;

    float acc[8][8] = {};
    float ks[8] = {};

    for (int lt = 0; lt < CH; lt += 16) {
        __syncthreads();
        {
            int row = tid >> 4;
            int c8 = tid & 15;
            int lg = c * CH + lt + row;
            const float* kb = g_Kf + ((size_t)p * Ll + lg) * DE + z * 128 + c8 * 8;
            const float* vb = V + (((size_t)(n * Ll + lg) * Hh) + h) * Dd + c8 * 8;
            *(float4*)&Kt[row][c8 * 8]     = *(const float4*)kb;
            *(float4*)&Kt[row][c8 * 8 + 4] = *(const float4*)(kb + 4);
            *(float4*)&Vt[row][c8 * 8]     = *(const float4*)vb;
            *(float4*)&Vt[row][c8 * 8 + 4] = *(const float4*)(vb + 4);
        }
        __syncthreads();
        #pragma unroll
        for (int l = 0; l < 16; l++) {
            float kr[8], vr[8];
            *(float4*)kr       = *(float4*)&Kt[l][i0];
            *(float4*)(kr + 4) = *(float4*)&Kt[l][i0 + 4];
            *(float4*)vr       = *(float4*)&Vt[l][j0];
            *(float4*)(vr + 4) = *(float4*)&Vt[l][j0 + 4];
            if (tx == 0) {
                #pragma unroll
                for (int ii = 0; ii < 8; ii++) ks[ii] += kr[ii];
            }
            #pragma unroll
            for (int ii = 0; ii < 8; ii++)
                #pragma unroll
                for (int jj = 0; jj < 8; jj++)
                    acc[ii][jj] = fmaf(kr[ii], vr[jj], acc[ii][jj]);
        }
    }

    float* sb = g_S + ((size_t)p * NCH + c) * DE * Dd;
    #pragma unroll
    for (int ii = 0; ii < 8; ii++) {
        float* row = sb + (size_t)(z * 128 + i0 + ii) * Dd + j0;
        *(float4*)row       = *(float4*)&acc[ii][0];
        *(float4*)(row + 4) = *(float4*)&acc[ii][4];
    }
    if (tx == 0) {
        float* kb = g_Ks + ((size_t)p * NCH + c) * DE + z * 128 + i0;
        #pragma unroll
        for (int ii = 0; ii < 8; ii++) kb[ii] = ks[ii];
    }
}

// ---------------------------------------------------------------------------
// Kernel B: in-place exclusive prefix over chunks of g_S and g_Ks.
// grid: (194, PAIRS), 256 threads; thread = one (i,j) entry.
// ---------------------------------------------------------------------------
__global__ void __launch_bounds__(256) k_prefix()
{
    const int p = blockIdx.y;
    const int e = blockIdx.x * 256 + threadIdx.x;
    if (e < DE * Dd) {
        float run = 0.0f;
        float* base = g_S + (size_t)p * NCH * DE * Dd + e;
        for (int c = 0; c < NCH; c++) {
            float v = base[(size_t)c * DE * Dd];
            base[(size_t)c * DE * Dd] = run;
            run += v;
        }
    } else {
        int ek = e - DE * Dd;
        if (ek < DE) {
            float run = 0.0f;
            float* base = g_Ks + (size_t)p * NCH * DE + ek;
            for (int c = 0; c < NCH; c++) {
                float v = base[c * DE];
                base[c * DE] = run;
                run += v;
            }
        }
    }
}

// ---------------------------------------------------------------------------
// Kernel C: per (chunk, pair): masked intra P=QK^T, inter Q*S_prev (+denominator
// via K prefix sums as virtual column), P*V, divide, write output [N,L,H,D].
// grid: (NCH, PAIRS), 256 threads, 4x8 micro-tile.
// ---------------------------------------------------------------------------
__device__ __forceinline__ void load_tileT(float T[][68], const float* __restrict__ src, int tid)
{
    // [64 rows][32 k] from row-major (stride DE) -> T[k][row]
    #pragma unroll
    for (int rep = 0; rep < 2; rep++) {
        int f = tid + rep * 256;
        int row = f >> 3;
        int c4 = f & 7;
        float4 v = *(const float4*)(src + (size_t)row * DE + c4 * 4);
        T[c4 * 4 + 0][row] = v.x;
        T[c4 * 4 + 1][row] = v.y;
        T[c4 * 4 + 2][row] = v.z;
        T[c4 * 4 + 3][row] = v.w;
    }
}

__global__ void __launch_bounds__(256) k_out(const float* __restrict__ V, float* __restrict__ OUT)
{
    __shared__ float Pt[64][68];     // masked P, transposed: Pt[s][l]
    __shared__ float QtT[32][68];    // Q tile transposed [k][l]
    __shared__ float Tb[32 * 132];   // union: KtT / St / Vt
    __shared__ float den[64];

    const int c = blockIdx.x, p = blockIdx.y;
    const int n = p >> 3, h = p & 7;
    const int tid = threadIdx.x;
    const int tx = tid & 15, ty = tid >> 4;

    const float* Qbase = g_Qf + ((size_t)p * Ll + c * CH) * DE;
    const float* Kbase = g_Kf + ((size_t)p * Ll + c * CH) * DE;

    // ---- phase 1: P[l][s] = sum_k Qf[l][k] Kf[s][k], causal mask ----
    float pacc[4][4] = {};
    float (*KtT)[68] = (float(*)[68])Tb;
    for (int k0 = 0; k0 < DE; k0 += 32) {
        __syncthreads();
        load_tileT(QtT, Qbase + k0, tid);
        load_tileT(KtT, Kbase + k0, tid);
        __syncthreads();
        #pragma unroll
        for (int k = 0; k < 32; k++) {
            float qr[4], kr[4];
            *(float4*)qr = *(float4*)&QtT[k][ty * 4];
            *(float4*)kr = *(float4*)&KtT[k][tx * 4];
            #pragma unroll
            for (int li = 0; li < 4; li++)
                #pragma unroll
                for (int si = 0; si < 4; si++)
                    pacc[li][si] = fmaf(qr[li], kr[si], pacc[li][si]);
        }
    }
    __syncthreads();
    #pragma unroll
    for (int li = 0; li < 4; li++) {
        int l = ty * 4 + li;
        #pragma unroll
        for (int si = 0; si < 4; si++) {
            int s = tx * 4 + si;
            Pt[s][l] = (s <= l) ? pacc[li][si] : 0.0f;
        }
    }
    __syncthreads();
    if (tid < 64) {               // intra denominator = row sum of masked P
        float sd = 0.0f;
        #pragma unroll
        for (int s = 0; s < 64; s++) sd += Pt[s][tid];
        den[tid] = sd;
    }

    // ---- phase 2a: inter-chunk  O += Q * S_prev, den += Q . ksumPrev ----
    float acc[4][8] = {};
    float dacc[4] = {};
    const float* Sb  = g_S  + ((size_t)p * NCH + c) * DE * Dd;
    const float* Ksb = g_Ks + ((size_t)p * NCH + c) * DE;
    float (*St)[132] = (float(*)[132])Tb;
    for (int k0 = 0; k0 < DE; k0 += 32) {
        __syncthreads();
        load_tileT(QtT, Qbase + k0, tid);
        #pragma unroll
        for (int rep = 0; rep < 4; rep++) {
            int f = tid + rep * 256;
            int row = f >> 5, c4 = f & 31;
            *(float4*)&St[row][c4 * 4] = *(const float4*)(Sb + (size_t)(k0 + row) * Dd + c4 * 4);
        }
        if (tid < 32) St[tid][128] = Ksb[k0 + tid];
        __syncthreads();
        #pragma unroll
        for (int k = 0; k < 32; k++) {
            float qr[4];
            *(float4*)qr = *(float4*)&QtT[k][ty * 4];
            float sr[8];
            *(float4*)sr       = *(float4*)&St[k][tx * 8];
            *(float4*)(sr + 4) = *(float4*)&St[k][tx * 8 + 4];
            #pragma unroll
            for (int li = 0; li < 4; li++)
                #pragma unroll
                for (int jj = 0; jj < 8; jj++)
                    acc[li][jj] = fmaf(qr[li], sr[jj], acc[li][jj]);
            if (tx == 15) {
                float kv = St[k][128];
                #pragma unroll
                for (int li = 0; li < 4; li++) dacc[li] = fmaf(qr[li], kv, dacc[li]);
            }
        }
    }
    __syncthreads();
    if (tx == 15) {
        #pragma unroll
        for (int li = 0; li < 4; li++) den[ty * 4 + li] += dacc[li];
    }

    // ---- phase 2b: intra  O += P * V ----
    float (*Vt)[132] = (float(*)[132])Tb;
    for (int s0 = 0; s0 < CH; s0 += 32) {
        __syncthreads();
        #pragma unroll
        for (int rep = 0; rep < 4; rep++) {
            int f = tid + rep * 256;
            int row = f >> 5, c4 = f & 31;
            int lg = c * CH + s0 + row;
            *(float4*)&Vt[row][c4 * 4] =
                *(const float4*)(V + (((size_t)(n * Ll + lg) * Hh) + h) * Dd + c4 * 4);
        }
        __syncthreads();
        #pragma unroll
        for (int s = 0; s < 32; s++) {
            float pr[4];
            *(float4*)pr = *(float4*)&Pt[s0 + s][ty * 4];
            float vr[8];
            *(float4*)vr       = *(float4*)&Vt[s][tx * 8];
            *(float4*)(vr + 4) = *(float4*)&Vt[s][tx * 8 + 4];
            #pragma unroll
            for (int li = 0; li < 4; li++)
                #pragma unroll
                for (int jj = 0; jj < 8; jj++)
                    acc[li][jj] = fmaf(pr[li], vr[jj], acc[li][jj]);
        }
    }
    __syncthreads();

    // ---- epilogue: divide and store ----
    #pragma unroll
    for (int li = 0; li < 4; li++) {
        int ll = ty * 4 + li;
        int lg = c * CH + ll;
        float dinv = 1.0f / (den[ll] + EPSF);
        float o[8];
        #pragma unroll
        for (int jj = 0; jj < 8; jj++) o[jj] = acc[li][jj] * dinv;
        float* ob = OUT + (((size_t)(n * Ll + lg) * Hh) + h) * Dd + tx * 8;
        *(float4*)ob       = *(float4*)o;
        *(float4*)(ob + 4) = *(float4*)(o + 4);
    }
}

// ---------------------------------------------------------------------------
extern "C" void kernel_launch(void* const* d_in, const int* in_sizes, int n_in,
                              void* d_out, int out_size)
{
    const float* q     = (const float*)d_in[0];
    const float* q2    = (const float*)d_in[1];
    const float* keys  = (const float*)d_in[2];
    const float* vals  = (const float*)d_in[3];
    const float* klen  = (const float*)d_in[4];
    const float* omega = (const float*)d_in[5];
    float* out = (float*)d_out;

    k_omsum<<<Hh, Dd>>>(omega);
    k_feat<<<dim3(Ll / 32, PAIRS), 256>>>(q, q2, keys, klen, omega);
    k_chunkKV<<<dim3(NCH, PAIRS, 3), 256>>>(vals);
    k_prefix<<<dim3((DE * Dd + DE + 255) / 256, PAIRS), 256>>>();
    k_out<<<dim3(NCH, PAIRS), 256>>>(vals, out);
    (void)in_sizes; (void)n_in; (void)out_size;
}

// round 17
// speedup vs baseline: 1.0691x; 1.0691x over previous
#include <cuda_runtime.h>
#include <math.h>

#define Nn 4
#define Ll 2048
#define Hh 8
#define Dd 128
#define PAIRS 32           // Nn*Hh
#define DE 384             // effective feature dim (3 branches x 128)
#define CH 64              // chunk length
#define NCH 32             // Ll / CH
#define EPSF 1e-6f

typedef unsigned long long u64;

// ---- packed fp32x2 helpers (Blackwell 2x FP32 path) ----
__device__ __forceinline__ u64 pk2(float a, float b) {
    u64 r; asm("mov.b64 %0, {%1, %2};" : "=l"(r) : "f"(a), "f"(b)); return r;
}
__device__ __forceinline__ u64 dup2(float a) { return pk2(a, a); }
__device__ __forceinline__ void up2(u64 v, float& a, float& b) {
    asm("mov.b64 {%0, %1}, %2;" : "=f"(a), "=f"(b) : "l"(v));
}
__device__ __forceinline__ void ffma2(u64& d, u64 a, u64 b) {
    asm("fma.rn.f32x2 %0, %1, %2, %0;" : "+l"(d) : "l"(a), "l"(b));
}
__device__ __forceinline__ u64 mul2(u64 a, u64 b) {
    u64 r; asm("mul.rn.f32x2 %0, %1, %2;" : "=l"(r) : "l"(a), "l"(b)); return r;
}

// ---- scratch (static device allocations; no cudaMalloc allowed) ----
__device__ float g_Qf[(size_t)PAIRS * Ll * DE];          // ~100.7 MB
__device__ float g_Kf[(size_t)PAIRS * Ll * DE];          // ~100.7 MB
__device__ float g_S [(size_t)PAIRS * NCH * DE * Dd];    // ~201 MB  chunk KV states
__device__ float g_Ks[(size_t)PAIRS * NCH * DE];         // chunk K column sums
__device__ float g_osum[Hh * Dd];

__device__ __forceinline__ float elu1(float x) { return x > 0.0f ? x + 1.0f : expf(x); }

// ---------------------------------------------------------------------------
// Kernel 0: omsum[h][j] = sum_i omega[h][i][j]
// ---------------------------------------------------------------------------
__global__ void k_omsum(const float* __restrict__ OMEGA)
{
    int h = blockIdx.x, j = threadIdx.x;
    const float* base = OMEGA + (size_t)h * Dd * Dd + j;
    float s = 0.0f;
    for (int i = 0; i < Dd; i++) s += base[(size_t)i * Dd];
    g_osum[h * Dd + j] = s;
}

// ---------------------------------------------------------------------------
// Kernel 1: features. q2_proj GEMM (tiled, f32x2) + trig epilogue -> g_Qf, g_Kf
// grid: (Ll/32, PAIRS), 256 threads. Thread (ty,tx) owns 4 l x 4 j.
// ---------------------------------------------------------------------------
__global__ void __launch_bounds__(256) k_feat(
    const float* __restrict__ Q, const float* __restrict__ Q2,
    const float* __restrict__ K, const float* __restrict__ KLEN,
    const float* __restrict__ OMEGA)
{
    __shared__ float Wt[32][132];   // omega tile [i][j]
    __shared__ float Q2t[32][36];   // q2 tile [l][i]
    __shared__ float osm[128];

    const int p = blockIdx.y;
    const int n = p >> 3, h = p & 7;
    const int l0g = blockIdx.x * 32;
    const int tid = threadIdx.x;
    const int tx = tid & 31, ty = tid >> 5;   // tx 0..31 (j-groups), ty 0..7 (l-groups)

    if (tid < 128) osm[tid] = g_osum[h * Dd + tid];

    const float* omh = OMEGA + (size_t)h * Dd * Dd;
    u64 acc2[4][2] = {};

    for (int i0 = 0; i0 < Dd; i0 += 32) {
        __syncthreads();
        {
            int c4 = tid & 31;
            int r0 = tid >> 5;
            #pragma unroll
            for (int rep = 0; rep < 4; rep++) {
                int row = r0 + rep * 8;
                float4 w = *(const float4*)(omh + (size_t)(i0 + row) * Dd + c4 * 4);
                *(float4*)&Wt[row][c4 * 4] = w;
            }
            int row = tid >> 3;
            int c4b = tid & 7;
            float4 qv = *(const float4*)(Q2 + (((size_t)(n * Ll + l0g + row) * Hh) + h) * Dd + i0 + c4b * 4);
            *(float4*)&Q2t[row][c4b * 4] = qv;
        }
        __syncthreads();
        #pragma unroll
        for (int i = 0; i < 32; i++) {
            const ulonglong2 w2 = *(const ulonglong2*)&Wt[i][tx * 4];
            #pragma unroll
            for (int li = 0; li < 4; li++) {
                u64 qq = dup2(Q2t[ty * 4 + li][i]);
                ffma2(acc2[li][0], qq, w2.x);
                ffma2(acc2[li][1], qq, w2.y);
            }
        }
    }

    const int j0 = tx * 4;
    #pragma unroll
    for (int li = 0; li < 4; li++) {
        float accs[4];
        up2(acc2[li][0], accs[0], accs[1]);
        up2(acc2[li][1], accs[2], accs[3]);
        int lg = l0g + ty * 4 + li;
        size_t ib = (((size_t)(n * Ll + lg) * Hh) + h) * Dd + j0;
        float4 qv = *(const float4*)(Q + ib);
        float4 kv = *(const float4*)(K + ib);
        float kl = KLEN[n * Ll + lg];
        float dl = (float)lg * (1.0f / (float)Ll);
        float qa[4] = {qv.x, qv.y, qv.z, qv.w};
        float ka[4] = {kv.x, kv.y, kv.z, kv.w};
        float qf0[4], qf1[4], qf2[4], kf0[4], kf1[4], kf2[4];
        #pragma unroll
        for (int jj = 0; jj < 4; jj++) {
            float t = dl * osm[j0 + jj];
            float s, c;
            sincosf(t, &s, &c);
            float sq = sinf(accs[jj]);              // sin(q2_proj)
            float A = sq * sq * elu1(qa[jj]);       // Q_term
            float B = elu1(ka[jj]) * kl;            // K feature
            float s2 = s * s, c2 = c * c, sc = s * c;
            qf0[jj] = A * s2;  qf1[jj] = A * c2;  qf2[jj] = -2.0f * A * sc;
            kf0[jj] = B * c2;  kf1[jj] = B * s2;  kf2[jj] = B * sc;
        }
        size_t ob = ((size_t)p * Ll + lg) * DE + j0;
        *(float4*)(g_Qf + ob)       = *(float4*)qf0;
        *(float4*)(g_Qf + ob + 128) = *(float4*)qf1;
        *(float4*)(g_Qf + ob + 256) = *(float4*)qf2;
        *(float4*)(g_Kf + ob)       = *(float4*)kf0;
        *(float4*)(g_Kf + ob + 128) = *(float4*)kf1;
        *(float4*)(g_Kf + ob + 256) = *(float4*)kf2;
    }
}

// ---------------------------------------------------------------------------
// Kernel A: per (chunk, pair, branch) compute S_c = K_c^T V_c  (128x128) and
// K column sums. grid: (NCH, PAIRS, 3), 256 threads, 8x8 micro-tile, f32x2.
// ---------------------------------------------------------------------------
__global__ void __launch_bounds__(256) k_chunkKV(const float* __restrict__ V)
{
    __shared__ float Kt[16][132];
    __shared__ float Vt[16][132];
    const int c = blockIdx.x, p = blockIdx.y, z = blockIdx.z;
    const int n = p >> 3, h = p & 7;
    const int tid = threadIdx.x;
    const int tx = tid & 15, ty = tid >> 4;
    const int i0 = ty * 8, j0 = tx * 8;

    u64 acc[8][4] = {};
    float ks[8] = {};

    for (int lt = 0; lt < CH; lt += 16) {
        __syncthreads();
        {
            int row = tid >> 4;
            int c8 = tid & 15;
            int lg = c * CH + lt + row;
            const float* kb = g_Kf + ((size_t)p * Ll + lg) * DE + z * 128 + c8 * 8;
            const float* vb = V + (((size_t)(n * Ll + lg) * Hh) + h) * Dd + c8 * 8;
            *(float4*)&Kt[row][c8 * 8]     = *(const float4*)kb;
            *(float4*)&Kt[row][c8 * 8 + 4] = *(const float4*)(kb + 4);
            *(float4*)&Vt[row][c8 * 8]     = *(const float4*)vb;
            *(float4*)&Vt[row][c8 * 8 + 4] = *(const float4*)(vb + 4);
        }
        __syncthreads();
        #pragma unroll
        for (int l = 0; l < 16; l++) {
            float kr[8];
            *(float4*)kr       = *(float4*)&Kt[l][i0];
            *(float4*)(kr + 4) = *(float4*)&Kt[l][i0 + 4];
            const ulonglong2 v0 = *(const ulonglong2*)&Vt[l][j0];
            const ulonglong2 v1 = *(const ulonglong2*)&Vt[l][j0 + 4];
            u64 vr[4] = {v0.x, v0.y, v1.x, v1.y};
            if (tx == 0) {
                #pragma unroll
                for (int ii = 0; ii < 8; ii++) ks[ii] += kr[ii];
            }
            #pragma unroll
            for (int ii = 0; ii < 8; ii++) {
                u64 kk = dup2(kr[ii]);
                #pragma unroll
                for (int jp = 0; jp < 4; jp++)
                    ffma2(acc[ii][jp], kk, vr[jp]);
            }
        }
    }

    float* sb = g_S + ((size_t)p * NCH + c) * DE * Dd;
    #pragma unroll
    for (int ii = 0; ii < 8; ii++) {
        float* row = sb + (size_t)(z * 128 + i0 + ii) * Dd + j0;
        ((ulonglong2*)row)[0] = make_ulonglong2(acc[ii][0], acc[ii][1]);
        ((ulonglong2*)row)[1] = make_ulonglong2(acc[ii][2], acc[ii][3]);
    }
    if (tx == 0) {
        float* kb = g_Ks + ((size_t)p * NCH + c) * DE + z * 128 + i0;
        #pragma unroll
        for (int ii = 0; ii < 8; ii++) kb[ii] = ks[ii];
    }
}

// ---------------------------------------------------------------------------
// Kernel B: in-place exclusive prefix over chunks of g_S and g_Ks.
// grid: (194, PAIRS), 256 threads; thread = one (i,j) entry.
// ---------------------------------------------------------------------------
__global__ void __launch_bounds__(256) k_prefix()
{
    const int p = blockIdx.y;
    const int e = blockIdx.x * 256 + threadIdx.x;
    if (e < DE * Dd) {
        float run = 0.0f;
        float* base = g_S + (size_t)p * NCH * DE * Dd + e;
        for (int c = 0; c < NCH; c++) {
            float v = base[(size_t)c * DE * Dd];
            base[(size_t)c * DE * Dd] = run;
            run += v;
        }
    } else {
        int ek = e - DE * Dd;
        if (ek < DE) {
            float run = 0.0f;
            float* base = g_Ks + (size_t)p * NCH * DE + ek;
            for (int c = 0; c < NCH; c++) {
                float v = base[c * DE];
                base[c * DE] = run;
                run += v;
            }
        }
    }
}

// ---------------------------------------------------------------------------
// Kernel C: per (chunk, pair): masked intra P=QK^T, inter Q*S_prev (+denominator
// via K prefix sums as virtual column), P*V, divide, write output [N,L,H,D].
// grid: (NCH, PAIRS), 256 threads, 4x8 micro-tile, f32x2 inner loops.
// ---------------------------------------------------------------------------
__device__ __forceinline__ void load_tileT(float T[][68], const float* __restrict__ src, int tid)
{
    // [64 rows][32 k] from row-major (stride DE) -> T[k][row]
    #pragma unroll
    for (int rep = 0; rep < 2; rep++) {
        int f = tid + rep * 256;
        int row = f >> 3;
        int c4 = f & 7;
        float4 v = *(const float4*)(src + (size_t)row * DE + c4 * 4);
        T[c4 * 4 + 0][row] = v.x;
        T[c4 * 4 + 1][row] = v.y;
        T[c4 * 4 + 2][row] = v.z;
        T[c4 * 4 + 3][row] = v.w;
    }
}

__global__ void __launch_bounds__(256) k_out(const float* __restrict__ V, float* __restrict__ OUT)
{
    __shared__ float Pt[64][68];     // masked P, transposed: Pt[s][l]
    __shared__ float QtT[32][68];    // Q tile transposed [k][l]
    __shared__ float Tb[32 * 132];   // union: KtT / St / Vt
    __shared__ float den[64];

    const int c = blockIdx.x, p = blockIdx.y;
    const int n = p >> 3, h = p & 7;
    const int tid = threadIdx.x;
    const int tx = tid & 15, ty = tid >> 4;

    const float* Qbase = g_Qf + ((size_t)p * Ll + c * CH) * DE;
    const float* Kbase = g_Kf + ((size_t)p * Ll + c * CH) * DE;

    // ---- phase 1: P[l][s] = sum_k Qf[l][k] Kf[s][k], causal mask ----
    u64 pacc[4][2] = {};
    float (*KtT)[68] = (float(*)[68])Tb;
    for (int k0 = 0; k0 < DE; k0 += 32) {
        __syncthreads();
        load_tileT(QtT, Qbase + k0, tid);
        load_tileT(KtT, Kbase + k0, tid);
        __syncthreads();
        #pragma unroll
        for (int k = 0; k < 32; k++) {
            float qr[4];
            *(float4*)qr = *(float4*)&QtT[k][ty * 4];
            const ulonglong2 k2 = *(const ulonglong2*)&KtT[k][tx * 4];
            #pragma unroll
            for (int li = 0; li < 4; li++) {
                u64 qq = dup2(qr[li]);
                ffma2(pacc[li][0], qq, k2.x);
                ffma2(pacc[li][1], qq, k2.y);
            }
        }
    }
    __syncthreads();
    #pragma unroll
    for (int li = 0; li < 4; li++) {
        int l = ty * 4 + li;
        float pv[4];
        up2(pacc[li][0], pv[0], pv[1]);
        up2(pacc[li][1], pv[2], pv[3]);
        #pragma unroll
        for (int si = 0; si < 4; si++) {
            int s = tx * 4 + si;
            Pt[s][l] = (s <= l) ? pv[si] : 0.0f;
        }
    }
    __syncthreads();
    if (tid < 64) {               // intra denominator = row sum of masked P
        float sd = 0.0f;
        #pragma unroll
        for (int s = 0; s < 64; s++) sd += Pt[s][tid];
        den[tid] = sd;
    }

    // ---- phase 2a: inter-chunk  O += Q * S_prev, den += Q . ksumPrev ----
    u64 acc[4][4] = {};
    float dacc[4] = {};
    const float* Sb  = g_S  + ((size_t)p * NCH + c) * DE * Dd;
    const float* Ksb = g_Ks + ((size_t)p * NCH + c) * DE;
    float (*St)[132] = (float(*)[132])Tb;
    for (int k0 = 0; k0 < DE; k0 += 32) {
        __syncthreads();
        load_tileT(QtT, Qbase + k0, tid);
        #pragma unroll
        for (int rep = 0; rep < 4; rep++) {
            int f = tid + rep * 256;
            int row = f >> 5, c4 = f & 31;
            *(float4*)&St[row][c4 * 4] = *(const float4*)(Sb + (size_t)(k0 + row) * Dd + c4 * 4);
        }
        if (tid < 32) St[tid][128] = Ksb[k0 + tid];
        __syncthreads();
        #pragma unroll
        for (int k = 0; k < 32; k++) {
            float qr[4];
            *(float4*)qr = *(float4*)&QtT[k][ty * 4];
            const ulonglong2 s0 = *(const ulonglong2*)&St[k][tx * 8];
            const ulonglong2 s1 = *(const ulonglong2*)&St[k][tx * 8 + 4];
            u64 sr[4] = {s0.x, s0.y, s1.x, s1.y};
            #pragma unroll
            for (int li = 0; li < 4; li++) {
                u64 qq = dup2(qr[li]);
                #pragma unroll
                for (int jp = 0; jp < 4; jp++)
                    ffma2(acc[li][jp], qq, sr[jp]);
            }
            if (tx == 15) {
                float kv = St[k][128];
                #pragma unroll
                for (int li = 0; li < 4; li++) dacc[li] = fmaf(qr[li], kv, dacc[li]);
            }
        }
    }
    __syncthreads();
    if (tx == 15) {
        #pragma unroll
        for (int li = 0; li < 4; li++) den[ty * 4 + li] += dacc[li];
    }

    // ---- phase 2b: intra  O += P * V ----
    float (*Vt)[132] = (float(*)[132])Tb;
    for (int s0 = 0; s0 < CH; s0 += 32) {
        __syncthreads();
        #pragma unroll
        for (int rep = 0; rep < 4; rep++) {
            int f = tid + rep * 256;
            int row = f >> 5, c4 = f & 31;
            int lg = c * CH + s0 + row;
            *(float4*)&Vt[row][c4 * 4] =
                *(const float4*)(V + (((size_t)(n * Ll + lg) * Hh) + h) * Dd + c4 * 4);
        }
        __syncthreads();
        #pragma unroll
        for (int s = 0; s < 32; s++) {
            float pr[4];
            *(float4*)pr = *(float4*)&Pt[s0 + s][ty * 4];
            const ulonglong2 v0 = *(const ulonglong2*)&Vt[s][tx * 8];
            const ulonglong2 v1 = *(const ulonglong2*)&Vt[s][tx * 8 + 4];
            u64 vr[4] = {v0.x, v0.y, v1.x, v1.y};
            #pragma unroll
            for (int li = 0; li < 4; li++) {
                u64 pp = dup2(pr[li]);
                #pragma unroll
                for (int jp = 0; jp < 4; jp++)
                    ffma2(acc[li][jp], pp, vr[jp]);
            }
        }
    }
    __syncthreads();

    // ---- epilogue: divide and store (packed) ----
    #pragma unroll
    for (int li = 0; li < 4; li++) {
        int ll = ty * 4 + li;
        int lg = c * CH + ll;
        u64 dinv2 = dup2(1.0f / (den[ll] + EPSF));
        float* ob = OUT + (((size_t)(n * Ll + lg) * Hh) + h) * Dd + tx * 8;
        ((ulonglong2*)ob)[0] = make_ulonglong2(mul2(acc[li][0], dinv2), mul2(acc[li][1], dinv2));
        ((ulonglong2*)ob)[1] = make_ulonglong2(mul2(acc[li][2], dinv2), mul2(acc[li][3], dinv2));
    }
}

// ---------------------------------------------------------------------------
extern "C" void kernel_launch(void* const* d_in, const int* in_sizes, int n_in,
                              void* d_out, int out_size)
{
    const float* q     = (const float*)d_in[0];
    const float* q2    = (const float*)d_in[1];
    const float* keys  = (const float*)d_in[2];
    const float* vals  = (const float*)d_in[3];
    const float* klen  = (const float*)d_in[4];
    const float* omega = (const float*)d_in[5];
    float* out = (float*)d_out;

    k_omsum<<<Hh, Dd>>>(omega);
    k_feat<<<dim3(Ll / 32, PAIRS), 256>>>(q, q2, keys, klen, omega);
    k_chunkKV<<<dim3(NCH, PAIRS, 3), 256>>>(vals);
    k_prefix<<<dim3((DE * Dd + DE + 255) / 256, PAIRS), 256>>>();
    k_out<<<dim3(NCH, PAIRS), 256>>>(vals, out);
    (void)in_sizes; (void)n_in; (void)out_size;
}